// round 1
// baseline (speedup 1.0000x reference)
#include <cuda_runtime.h>
#include <cstdint>

#define BATCH 8
#define SEQ   4096
#define DIM   1024
#define RNK   64

#define QB 64      // query tile rows
#define KB 64      // key tile rows
#define DS 256     // D-slice per CTA

// scratch for projected P = x @ (Q / sqrt(D)), layout [BATCH*SEQ][RNK]
__device__ float g_P[BATCH * SEQ * RNK];

// ---------------------------------------------------------------------------
// fast exp for x <= 0 (FMA pipe only; avoids MUFU throughput wall)
// exp(x) = 2^n * exp(u), n = rint(x*log2e), u = (x*log2e - n)*ln2, |u| <= 0.347
// ---------------------------------------------------------------------------
__device__ __forceinline__ float fexp(float x) {
    float t = x * 1.4426950408889634f;
    t = fmaxf(t, -126.0f);
    float n = rintf(t);
    float u = (t - n) * 0.6931471805599453f;
    float p = 1.38888889e-3f;              // 1/720
    p = fmaf(p, u, 8.33333333e-3f);        // 1/120
    p = fmaf(p, u, 4.16666667e-2f);        // 1/24
    p = fmaf(p, u, 1.66666667e-1f);        // 1/6
    p = fmaf(p, u, 0.5f);
    p = fmaf(p, u, 1.0f);
    p = fmaf(p, u, 1.0f);
    float s = __int_as_float(((int)n + 127) << 23);
    return p * s;
}

// ---------------------------------------------------------------------------
// Projection: P[row][r] = sum_d x[row][d] * Q[d][r] * (1/32)
// block = 64 rows x 64 cols, 256 threads, 4x4 register tile each
// ---------------------------------------------------------------------------
__global__ __launch_bounds__(256, 2)
void proj_kernel(const float* __restrict__ x, const float* __restrict__ Q) {
    __shared__ float XsT[64 * 64];   // [l][row], chunk-swizzled
    __shared__ float Qs[64 * 64];    // [l][r]

    const int t   = threadIdx.x;
    const int row0 = blockIdx.x * 64;
    const int ty = t >> 4, tx = t & 15;

    float acc[4][4];
#pragma unroll
    for (int i = 0; i < 4; i++)
#pragma unroll
        for (int j = 0; j < 4; j++) acc[i][j] = 0.f;

    for (int d0 = 0; d0 < DIM; d0 += 64) {
        __syncthreads();
        // load x tile [64 rows][64 d] transposed into XsT[l][row] (swizzled chunks)
        {
            const int r = t >> 2;
            const int lbase = (t & 3) << 4;
            const float* xp = x + (size_t)(row0 + r) * DIM + d0 + lbase;
#pragma unroll
            for (int m = 0; m < 4; m++) {
                float4 v = *(const float4*)(xp + 4 * m);
                float vv[4] = {v.x, v.y, v.z, v.w};
#pragma unroll
                for (int k = 0; k < 4; k++) {
                    int l = lbase + 4 * m + k;
                    int phys = (((r >> 2) ^ (l & 15)) << 2) | (r & 3);
                    XsT[l * 64 + phys] = vv[k];
                }
            }
            // load Q tile [64 d][64 r] natural layout
            const int lq = t >> 2;
            const int cb = (t & 3) << 4;
            const float* qp = Q + (size_t)(d0 + lq) * RNK + cb;
#pragma unroll
            for (int m = 0; m < 4; m++)
                *(float4*)&Qs[lq * 64 + cb + 4 * m] = *(const float4*)(qp + 4 * m);
        }
        __syncthreads();

#pragma unroll 4
        for (int l = 0; l < 64; l++) {
            float4 a4 = *(const float4*)&XsT[l * 64 + ((ty ^ (l & 15)) << 2)];
            float4 b4 = *(const float4*)&Qs[l * 64 + (tx << 2)];
            float a[4] = {a4.x, a4.y, a4.z, a4.w};
            float b[4] = {b4.x, b4.y, b4.z, b4.w};
#pragma unroll
            for (int i = 0; i < 4; i++)
#pragma unroll
                for (int j = 0; j < 4; j++)
                    acc[i][j] = fmaf(a[i], b[j], acc[i][j]);
        }
    }

    const float scale = 0.03125f;  // 1/sqrt(1024)
#pragma unroll
    for (int i = 0; i < 4; i++) {
        float4 o;
        o.x = acc[i][0] * scale; o.y = acc[i][1] * scale;
        o.z = acc[i][2] * scale; o.w = acc[i][3] * scale;
        *(float4*)&g_P[(size_t)(row0 + ty * 4 + i) * RNK + (tx << 2)] = o;
    }
}

// ---------------------------------------------------------------------------
// Flash attention: grid (SEQ/QB, BATCH, DIM/DS), 256 threads
// ---------------------------------------------------------------------------
__global__ __launch_bounds__(256, 1)
void attn_kernel(const float* __restrict__ x, float* __restrict__ out) {
    extern __shared__ float sm[];
    float* PqT = sm;               // [64 l][64 row]  swizzled
    float* PkT = PqT + 64 * 64;    // [64 l][64 col]  swizzled
    float* Pt  = PkT + 64 * 64;    // [64 row][64 k]  probs
    float* Vs  = Pt + 64 * 64;     // [64 k][256 c]
    float* m_s = Vs + 64 * DS;     // [64]
    float* l_s = m_s + 64;         // [64]
    float* a_s = l_s + 64;         // [64]

    const int t  = threadIdx.x;
    const int qb = blockIdx.x, b = blockIdx.y, z = blockIdx.z;
    const size_t srow0 = (size_t)b * SEQ + (size_t)qb * QB;
    const float* Pbase = g_P + (size_t)b * SEQ * RNK;

    const int ty = t >> 4, tx = t & 15;    // QK mapping (16x16 thr, 4x4 tile)
    const int g_r = t >> 5, g_c = t & 31;  // PV mapping (8x32 thr, 8x8 tile)

    // load PqT (transpose + swizzle)
    {
        const int r = t >> 2;
        const int lbase = (t & 3) << 4;
        const float* pp = g_P + (srow0 + r) * RNK + lbase;
#pragma unroll
        for (int m = 0; m < 4; m++) {
            float4 v = *(const float4*)(pp + 4 * m);
            float vv[4] = {v.x, v.y, v.z, v.w};
#pragma unroll
            for (int k = 0; k < 4; k++) {
                int l = lbase + 4 * m + k;
                int phys = (((r >> 2) ^ (l & 15)) << 2) | (r & 3);
                PqT[l * 64 + phys] = vv[k];
            }
        }
    }
    if (t < 64) { m_s[t] = -1e30f; l_s[t] = 0.f; }

    float O[8][8];
#pragma unroll
    for (int i = 0; i < 8; i++)
#pragma unroll
        for (int j = 0; j < 8; j++) O[i][j] = 0.f;

    for (int kt = 0; kt < SEQ / KB; kt++) {
        __syncthreads();  // previous PV done with Pt/Vs/a_s

        // --- load PkT (transpose+swizzle) and Vs tile ---
        {
            const int r = t >> 2;
            const int lbase = (t & 3) << 4;
            const float* pp = Pbase + (size_t)(kt * KB + r) * RNK + lbase;
#pragma unroll
            for (int m = 0; m < 4; m++) {
                float4 v = *(const float4*)(pp + 4 * m);
                float vv[4] = {v.x, v.y, v.z, v.w};
#pragma unroll
                for (int k = 0; k < 4; k++) {
                    int l = lbase + 4 * m + k;
                    int phys = (((r >> 2) ^ (l & 15)) << 2) | (r & 3);
                    PkT[l * 64 + phys] = vv[k];
                }
            }
            const float* vb = x + ((size_t)b * SEQ + (size_t)kt * KB) * DIM + z * DS;
#pragma unroll
            for (int m = 0; m < 16; m++) {
                int idx = t + 256 * m;           // float4 index
                int k = idx >> 6;                // /64
                int c = (idx & 63) << 2;
                *(float4*)&Vs[k * DS + c] = *(const float4*)(vb + (size_t)k * DIM + c);
            }
        }
        __syncthreads();

        // --- QK^T: 4x4 per thread ---
        float acc[4][4];
#pragma unroll
        for (int i = 0; i < 4; i++)
#pragma unroll
            for (int j = 0; j < 4; j++) acc[i][j] = 0.f;

#pragma unroll 4
        for (int l = 0; l < 64; l++) {
            float4 a4 = *(const float4*)&PqT[l * 64 + ((ty ^ (l & 15)) << 2)];
            float4 b4 = *(const float4*)&PkT[l * 64 + ((tx ^ (l & 15)) << 2)];
            float a[4] = {a4.x, a4.y, a4.z, a4.w};
            float bb[4] = {b4.x, b4.y, b4.z, b4.w};
#pragma unroll
            for (int i = 0; i < 4; i++)
#pragma unroll
                for (int j = 0; j < 4; j++)
                    acc[i][j] = fmaf(a[i], bb[j], acc[i][j]);
        }

        // --- online softmax ---
        const int rowb = ty * 4;
        float tm[4], rs[4];
#pragma unroll
        for (int i = 0; i < 4; i++) {
            tm[i] = fmaxf(fmaxf(acc[i][0], acc[i][1]), fmaxf(acc[i][2], acc[i][3]));
        }
#pragma unroll
        for (int w = 1; w <= 8; w <<= 1)
#pragma unroll
            for (int i = 0; i < 4; i++)
                tm[i] = fmaxf(tm[i], __shfl_xor_sync(0xffffffffu, tm[i], w));

        float mo[4], mn[4], al[4];
#pragma unroll
        for (int i = 0; i < 4; i++) {
            mo[i] = m_s[rowb + i];
            mn[i] = fmaxf(mo[i], tm[i]);
            al[i] = fexp(mo[i] - mn[i]);
            rs[i] = 0.f;
        }
#pragma unroll
        for (int i = 0; i < 4; i++)
#pragma unroll
            for (int j = 0; j < 4; j++) {
                float p = fexp(acc[i][j] - mn[i]);
                acc[i][j] = p;
                rs[i] += p;
            }
#pragma unroll
        for (int w = 1; w <= 8; w <<= 1)
#pragma unroll
            for (int i = 0; i < 4; i++)
                rs[i] += __shfl_xor_sync(0xffffffffu, rs[i], w);

        if (tx == 0) {
#pragma unroll
            for (int i = 0; i < 4; i++) {
                m_s[rowb + i] = mn[i];
                l_s[rowb + i] = l_s[rowb + i] * al[i] + rs[i];
                a_s[rowb + i] = al[i];
            }
        }
        // write probs
#pragma unroll
        for (int i = 0; i < 4; i++) {
            float4 o; o.x = acc[i][0]; o.y = acc[i][1]; o.z = acc[i][2]; o.w = acc[i][3];
            *(float4*)&Pt[(rowb + i) * 64 + (tx << 2)] = o;
        }
        __syncthreads();

        // --- PV: O[8][8] accumulate ---
        {
            float av[8];
#pragma unroll
            for (int i = 0; i < 8; i++) av[i] = a_s[g_r * 8 + i];
#pragma unroll
            for (int i = 0; i < 8; i++)
#pragma unroll
                for (int j = 0; j < 8; j++) O[i][j] *= av[i];

#pragma unroll 2
            for (int k = 0; k < 64; k += 4) {
                float4 p4[8];
#pragma unroll
                for (int i = 0; i < 8; i++)
                    p4[i] = *(const float4*)&Pt[(g_r * 8 + i) * 64 + k];
                float pe[8][4];
#pragma unroll
                for (int i = 0; i < 8; i++) {
                    pe[i][0] = p4[i].x; pe[i][1] = p4[i].y;
                    pe[i][2] = p4[i].z; pe[i][3] = p4[i].w;
                }
#pragma unroll
                for (int kk = 0; kk < 4; kk++) {
                    float4 v0 = *(const float4*)&Vs[(k + kk) * DS + (g_c << 2)];
                    float4 v1 = *(const float4*)&Vs[(k + kk) * DS + 128 + (g_c << 2)];
                    float ve[8] = {v0.x, v0.y, v0.z, v0.w, v1.x, v1.y, v1.z, v1.w};
#pragma unroll
                    for (int i = 0; i < 8; i++) {
                        float p = pe[i][kk];
#pragma unroll
                        for (int j = 0; j < 8; j++)
                            O[i][j] = fmaf(p, ve[j], O[i][j]);
                    }
                }
            }
        }
    }

    __syncthreads();
    // normalize and store
#pragma unroll
    for (int i = 0; i < 8; i++) {
        float linv = 1.0f / l_s[g_r * 8 + i];
        float* op = out + (srow0 + g_r * 8 + i) * DIM + z * DS;
        float4 o0, o1;
        o0.x = O[i][0] * linv; o0.y = O[i][1] * linv;
        o0.z = O[i][2] * linv; o0.w = O[i][3] * linv;
        o1.x = O[i][4] * linv; o1.y = O[i][5] * linv;
        o1.z = O[i][6] * linv; o1.w = O[i][7] * linv;
        *(float4*)(op + (g_c << 2)) = o0;
        *(float4*)(op + 128 + (g_c << 2)) = o1;
    }
}

// ---------------------------------------------------------------------------
extern "C" void kernel_launch(void* const* d_in, const int* in_sizes, int n_in,
                              void* d_out, int out_size) {
    const float* x = (const float*)d_in[0];
    const float* Q = (const float*)d_in[1];
    float* out = (float*)d_out;

    const int smem_bytes = (3 * 64 * 64 + 64 * DS + 3 * 64) * (int)sizeof(float);
    cudaFuncSetAttribute(attn_kernel, cudaFuncAttributeMaxDynamicSharedMemorySize,
                         smem_bytes);

    proj_kernel<<<(BATCH * SEQ) / 64, 256>>>(x, Q);
    attn_kernel<<<dim3(SEQ / QB, BATCH, DIM / DS), 256, smem_bytes>>>(x, out);
}

// round 3
// speedup vs baseline: 2.7231x; 2.7231x over previous
#include <cuda_runtime.h>
#include <cuda_bf16.h>
#include <cstdint>

#define BATCH 8
#define SEQ   4096
#define DIM   1024
#define RNK   64
#define KB    64
#define NIT   (SEQ/KB)

// ---------------- global scratch ----------------
__device__ __align__(16) __nv_bfloat16 g_P_hi[BATCH * SEQ * RNK];
__device__ __align__(16) __nv_bfloat16 g_P_lo[BATCH * SEQ * RNK];
__device__ __align__(16) __nv_bfloat16 g_x_hi[(size_t)BATCH * SEQ * DIM];
__device__ __align__(16) __nv_bfloat16 g_x_lo[(size_t)BATCH * SEQ * DIM];

// ---------------- helpers ----------------
__device__ __forceinline__ uint32_t smem_u32(const void* p) {
    uint32_t a;
    asm("{ .reg .u64 t; cvta.to.shared.u64 t, %1; cvt.u32.u64 %0, t; }" : "=r"(a) : "l"(p));
    return a;
}
__device__ __forceinline__ void ldsm4(uint32_t* r, uint32_t a) {
    asm volatile("ldmatrix.sync.aligned.m8n8.x4.shared.b16 {%0,%1,%2,%3}, [%4];"
        : "=r"(r[0]), "=r"(r[1]), "=r"(r[2]), "=r"(r[3]) : "r"(a));
}
__device__ __forceinline__ void ldsm4t(uint32_t* r, uint32_t a) {
    asm volatile("ldmatrix.sync.aligned.m8n8.x4.trans.shared.b16 {%0,%1,%2,%3}, [%4];"
        : "=r"(r[0]), "=r"(r[1]), "=r"(r[2]), "=r"(r[3]) : "r"(a));
}
__device__ __forceinline__ void mma16816(float* d, const uint32_t* a, const uint32_t* b) {
    asm volatile(
        "mma.sync.aligned.m16n8k16.row.col.f32.bf16.bf16.f32 "
        "{%0,%1,%2,%3}, {%4,%5,%6,%7}, {%8,%9}, {%0,%1,%2,%3};"
        : "+f"(d[0]), "+f"(d[1]), "+f"(d[2]), "+f"(d[3])
        : "r"(a[0]), "r"(a[1]), "r"(a[2]), "r"(a[3]), "r"(b[0]), "r"(b[1]));
}
// split two floats into packed bf16 hi and packed bf16 residual-lo
__device__ __forceinline__ void split2(float a, float b, uint32_t& hi, uint32_t& lo) {
    __nv_bfloat16 ha = __float2bfloat16(a), hb = __float2bfloat16(b);
    hi = ((uint32_t)(*(uint16_t*)&hb) << 16) | (uint32_t)(*(uint16_t*)&ha);
    float ra = a - __bfloat162float(ha), rb = b - __bfloat162float(hb);
    __nv_bfloat16 la = __float2bfloat16(ra), lb = __float2bfloat16(rb);
    lo = ((uint32_t)(*(uint16_t*)&lb) << 16) | (uint32_t)(*(uint16_t*)&la);
}
// fast exp on FMA pipe, |x| <= ~80
__device__ __forceinline__ float fexp(float x) {
    float t = x * 1.4426950408889634f;
    t = fmaxf(t, -126.0f);
    float n = rintf(t);
    float u = (t - n) * 0.6931471805599453f;
    float p = 1.38888889e-3f;
    p = fmaf(p, u, 8.33333333e-3f);
    p = fmaf(p, u, 4.16666667e-2f);
    p = fmaf(p, u, 1.66666667e-1f);
    p = fmaf(p, u, 0.5f);
    p = fmaf(p, u, 1.0f);
    p = fmaf(p, u, 1.0f);
    float s = __int_as_float(((int)n + 127) << 23);
    return p * s;
}

// ---------------------------------------------------------------------------
// Pre-pass 1: P = x @ (Q/32) -> bf16 hi/lo   (fp32 SIMT, small GEMM)
// ---------------------------------------------------------------------------
__global__ __launch_bounds__(256, 2)
void proj_kernel(const float* __restrict__ x, const float* __restrict__ Q) {
    __shared__ float XsT[64 * 64];
    __shared__ float Qs[64 * 64];
    const int t = threadIdx.x;
    const int row0 = blockIdx.x * 64;
    const int ty = t >> 4, tx = t & 15;

    float acc[4][4];
#pragma unroll
    for (int i = 0; i < 4; i++)
#pragma unroll
        for (int j = 0; j < 4; j++) acc[i][j] = 0.f;

    for (int d0 = 0; d0 < DIM; d0 += 64) {
        __syncthreads();
        {
            const int r = t >> 2;
            const int lbase = (t & 3) << 4;
            const float* xp = x + (size_t)(row0 + r) * DIM + d0 + lbase;
#pragma unroll
            for (int m = 0; m < 4; m++) {
                float4 v = *(const float4*)(xp + 4 * m);
                float vv[4] = {v.x, v.y, v.z, v.w};
#pragma unroll
                for (int k = 0; k < 4; k++) {
                    int l = lbase + 4 * m + k;
                    int phys = (((r >> 2) ^ (l & 15)) << 2) | (r & 3);
                    XsT[l * 64 + phys] = vv[k];
                }
            }
            const int lq = t >> 2;
            const int cb = (t & 3) << 4;
            const float* qp = Q + (size_t)(d0 + lq) * RNK + cb;
#pragma unroll
            for (int m = 0; m < 4; m++)
                *(float4*)&Qs[lq * 64 + cb + 4 * m] = *(const float4*)(qp + 4 * m);
        }
        __syncthreads();
#pragma unroll 4
        for (int l = 0; l < 64; l++) {
            float4 a4 = *(const float4*)&XsT[l * 64 + ((ty ^ (l & 15)) << 2)];
            float4 b4 = *(const float4*)&Qs[l * 64 + (tx << 2)];
            float a[4] = {a4.x, a4.y, a4.z, a4.w};
            float b[4] = {b4.x, b4.y, b4.z, b4.w};
#pragma unroll
            for (int i = 0; i < 4; i++)
#pragma unroll
                for (int j = 0; j < 4; j++)
                    acc[i][j] = fmaf(a[i], b[j], acc[i][j]);
        }
    }
    const float scale = 0.03125f;
#pragma unroll
    for (int i = 0; i < 4; i++) {
        size_t base = (size_t)(row0 + ty * 4 + i) * RNK + tx * 4;
#pragma unroll
        for (int jp = 0; jp < 2; jp++) {
            uint32_t hi, lo;
            split2(acc[i][2 * jp] * scale, acc[i][2 * jp + 1] * scale, hi, lo);
            *(uint32_t*)&g_P_hi[base + 2 * jp] = hi;
            *(uint32_t*)&g_P_lo[base + 2 * jp] = lo;
        }
    }
}

// ---------------------------------------------------------------------------
// Pre-pass 2: x fp32 -> bf16 hi/lo (same layout, elementwise)
// ---------------------------------------------------------------------------
__global__ __launch_bounds__(256)
void cvt_kernel(const float* __restrict__ x) {
    size_t idx = (size_t)blockIdx.x * 256 + threadIdx.x;   // float4 index
    float4 v = ((const float4*)x)[idx];
    uint32_t h0, l0, h1, l1;
    split2(v.x, v.y, h0, l0);
    split2(v.z, v.w, h1, l1);
    ((uint2*)g_x_hi)[idx] = make_uint2(h0, h1);
    ((uint2*)g_x_lo)[idx] = make_uint2(l0, l1);
}

// ---------------------------------------------------------------------------
// Flash attention via mma.sync bf16. grid (32 qtiles, 4 d-slices, 8 batches)
// ---------------------------------------------------------------------------
#define OFF_PQH 0
#define OFF_PQL 16384
#define OFF_PKH 32768
#define OFF_PKL 40960
#define OFF_VH  49152
#define OFF_VL  81920
#define SMEM_TOTAL 114688

__global__ __launch_bounds__(256, 1)
void attn_kernel(float* __restrict__ out) {
    extern __shared__ char sm[];
    const uint32_t smb = smem_u32(sm);
    const int t = threadIdx.x;
    const int warp = t >> 5, lane = t & 31;
    const int qb = blockIdx.x, z = blockIdx.y, b = blockIdx.z;
    const int q0 = warp * 16;
    const int tg = lane & 3, g = lane >> 2;
    const int i7 = lane & 7, grp = lane >> 3;

    // ---- load Pq tile [128 q][64 r] hi/lo into smem (swizzled) ----
#pragma unroll
    for (int m = 0; m < 4; m++) {
        int idx = t + 256 * m;
        int row = idx >> 3, ch = idx & 7;
        size_t src = ((size_t)b * SEQ + (size_t)qb * 128 + row) * RNK + ch * 8;
        uint32_t dst = row * 128 + (((uint32_t)(ch ^ (row & 7))) << 4);
        *(uint4*)(sm + OFF_PQH + dst) = *(const uint4*)(g_P_hi + src);
        *(uint4*)(sm + OFF_PQL + dst) = *(const uint4*)(g_P_lo + src);
    }

    float Y[32][4];
#pragma unroll
    for (int n = 0; n < 32; n++)
#pragma unroll
        for (int e = 0; e < 4; e++) Y[n][e] = 0.f;
    float Ll = 0.f, Lh = 0.f;

    // per-lane ldmatrix address components
    const uint32_t rowA = q0 + i7 + ((grp & 1) << 3);     // Pq A-frag row
    const uint32_t cselA = grp >> 1;
    const uint32_t aBase = smb + OFF_PQH + rowA * 128;
    const uint32_t rowB = i7 + ((grp >> 1) << 3);         // Pk B-frag row offset
    const uint32_t cselB = grp & 1;
    const uint32_t rowV = i7 + ((grp & 1) << 3);          // V B-frag row offset
    const uint32_t cselV = grp >> 1;

    const __nv_bfloat16* pk_h = g_P_hi + (size_t)b * SEQ * RNK;
    const __nv_bfloat16* pk_l = g_P_lo + (size_t)b * SEQ * RNK;
    const __nv_bfloat16* vh_g = g_x_hi + (size_t)b * SEQ * DIM + (size_t)z * 256;
    const __nv_bfloat16* vl_g = g_x_lo + (size_t)b * SEQ * DIM + (size_t)z * 256;

    for (int it = 0; it < NIT; it++) {
        const int k0 = it * KB;
        __syncthreads();   // previous iter's ldmatrix reads done

        // ---- load Pk [64 k][64 r] hi/lo ----
#pragma unroll
        for (int m = 0; m < 2; m++) {
            int idx = t + 256 * m;
            int row = idx >> 3, ch = idx & 7;
            size_t src = (size_t)(k0 + row) * RNK + ch * 8;
            uint32_t dst = row * 128 + (((uint32_t)(ch ^ (row & 7))) << 4);
            *(uint4*)(sm + OFF_PKH + dst) = *(const uint4*)(pk_h + src);
            *(uint4*)(sm + OFF_PKL + dst) = *(const uint4*)(pk_l + src);
        }
        // ---- load V [64 k][256 d] hi/lo ----
#pragma unroll
        for (int m = 0; m < 8; m++) {
            int idx = t + 256 * m;
            int row = idx >> 5, ch = idx & 31;
            size_t src = (size_t)(k0 + row) * DIM + ch * 8;
            uint32_t dst = row * 512 + (((uint32_t)(ch ^ (row & 7))) << 4);
            *(uint4*)(sm + OFF_VH + dst) = *(const uint4*)(vh_g + src);
            *(uint4*)(sm + OFF_VL + dst) = *(const uint4*)(vl_g + src);
        }
        __syncthreads();

        // ---- QK^T: S[16 q][64 k] in d-fragments ----
        float S[8][4];
#pragma unroll
        for (int n = 0; n < 8; n++)
#pragma unroll
            for (int e = 0; e < 4; e++) S[n][e] = 0.f;

#pragma unroll
        for (int kt = 0; kt < 4; kt++) {
            uint32_t ah[4], al[4];
            uint32_t aaddr = aBase + ((((kt << 1) + cselA) ^ i7) << 4);
            ldsm4(ah, aaddr);
            ldsm4(al, aaddr + (OFF_PQL - OFF_PQH));
#pragma unroll
            for (int np = 0; np < 4; np++) {
                uint32_t bh[4], bl[4];
                uint32_t baddr = smb + OFF_PKH + ((np << 4) + rowB) * 128
                               + ((((kt << 1) + cselB) ^ i7) << 4);
                ldsm4(bh, baddr);
                ldsm4(bl, baddr + (OFF_PKL - OFF_PKH));
                mma16816(S[2 * np],     ah, bh + 0);
                mma16816(S[2 * np],     ah, bl + 0);
                mma16816(S[2 * np],     al, bh + 0);
                mma16816(S[2 * np + 1], ah, bh + 2);
                mma16816(S[2 * np + 1], ah, bl + 2);
                mma16816(S[2 * np + 1], al, bh + 2);
            }
        }

        // ---- softmax (no max subtraction: |logits| <= ~3) ----
        float rl = 0.f, rh = 0.f;
#pragma unroll
        for (int n = 0; n < 8; n++) {
            S[n][0] = fexp(S[n][0]);
            S[n][1] = fexp(S[n][1]);
            S[n][2] = fexp(S[n][2]);
            S[n][3] = fexp(S[n][3]);
            rl += S[n][0] + S[n][1];
            rh += S[n][2] + S[n][3];
        }
        rl += __shfl_xor_sync(0xffffffffu, rl, 1);
        rl += __shfl_xor_sync(0xffffffffu, rl, 2);
        rh += __shfl_xor_sync(0xffffffffu, rh, 1);
        rh += __shfl_xor_sync(0xffffffffu, rh, 2);
        Ll += rl;
        Lh += rh;

        // repack probs into PV A-fragments (hi + residual lo)
        uint32_t Ph[4][4], Pl[4][4];
#pragma unroll
        for (int kt = 0; kt < 4; kt++) {
            int n0 = 2 * kt;
            split2(S[n0][0],     S[n0][1],     Ph[kt][0], Pl[kt][0]);
            split2(S[n0][2],     S[n0][3],     Ph[kt][1], Pl[kt][1]);
            split2(S[n0 + 1][0], S[n0 + 1][1], Ph[kt][2], Pl[kt][2]);
            split2(S[n0 + 1][2], S[n0 + 1][3], Ph[kt][3], Pl[kt][3]);
        }

        // ---- PV: Y[16 q][256 d] += P @ V ----
#pragma unroll
        for (int kt = 0; kt < 4; kt++) {
            uint32_t vrow = smb + OFF_VH + ((kt << 4) + rowV) * 512;
#pragma unroll
            for (int np = 0; np < 16; np++) {
                uint32_t vaddr = vrow + ((((np << 1) + cselV) ^ i7) << 4);
                uint32_t bh[4], bl[4];
                ldsm4t(bh, vaddr);
                ldsm4t(bl, vaddr + (OFF_VL - OFF_VH));
                mma16816(Y[2 * np],     Ph[kt], bh + 0);
                mma16816(Y[2 * np],     Ph[kt], bl + 0);
                mma16816(Y[2 * np],     Pl[kt], bh + 0);
                mma16816(Y[2 * np + 1], Ph[kt], bh + 2);
                mma16816(Y[2 * np + 1], Ph[kt], bl + 2);
                mma16816(Y[2 * np + 1], Pl[kt], bh + 2);
            }
        }
    }

    // ---- epilogue: normalize rows, store ----
    const float il = 1.0f / Ll;
    const float ih = 1.0f / Lh;
    const int rlo = qb * 128 + q0 + g;
    float* o_lo = out + ((size_t)b * SEQ + rlo) * DIM + (size_t)z * 256 + 2 * tg;
    float* o_hi = o_lo + (size_t)8 * DIM;
#pragma unroll
    for (int n = 0; n < 32; n++) {
        float2 p;
        p.x = Y[n][0] * il; p.y = Y[n][1] * il;
        *(float2*)(o_lo + 8 * n) = p;
        p.x = Y[n][2] * ih; p.y = Y[n][3] * ih;
        *(float2*)(o_hi + 8 * n) = p;
    }
}

// ---------------------------------------------------------------------------
extern "C" void kernel_launch(void* const* d_in, const int* in_sizes, int n_in,
                              void* d_out, int out_size) {
    const float* x = (const float*)d_in[0];
    const float* Q = (const float*)d_in[1];
    float* out = (float*)d_out;

    cudaFuncSetAttribute(attn_kernel, cudaFuncAttributeMaxDynamicSharedMemorySize,
                         SMEM_TOTAL);

    proj_kernel<<<(BATCH * SEQ) / 64, 256>>>(x, Q);
    cvt_kernel<<<(BATCH * SEQ * DIM / 4) / 256, 256>>>(x);
    attn_kernel<<<dim3(SEQ / 128, DIM / 256, BATCH), 256, SMEM_TOTAL>>>(out);
}

// round 4
// speedup vs baseline: 6.1124x; 2.2447x over previous
#include <cuda_runtime.h>
#include <cuda_fp16.h>
#include <cstdint>

#define BATCH 8
#define SEQ   4096
#define DIM   1024
#define RNK   64
#define KB    64
#define NIT   (SEQ/KB)

// ---------------- global scratch ----------------
__device__ __align__(16) __half g_P_hi[BATCH * SEQ * RNK];
__device__ __align__(16) __half g_P_lo[BATCH * SEQ * RNK];
__device__ __align__(16) __half g_xh[(size_t)BATCH * SEQ * DIM];
__device__ __align__(16) float  g_csum[BATCH * DIM];

// ---------------- helpers ----------------
__device__ __forceinline__ uint32_t smem_u32(const void* p) {
    uint32_t a;
    asm("{ .reg .u64 t; cvta.to.shared.u64 t, %1; cvt.u32.u64 %0, t; }" : "=r"(a) : "l"(p));
    return a;
}
__device__ __forceinline__ void ldsm4(uint32_t* r, uint32_t a) {
    asm volatile("ldmatrix.sync.aligned.m8n8.x4.shared.b16 {%0,%1,%2,%3}, [%4];"
        : "=r"(r[0]), "=r"(r[1]), "=r"(r[2]), "=r"(r[3]) : "r"(a));
}
__device__ __forceinline__ void ldsm4t(uint32_t* r, uint32_t a) {
    asm volatile("ldmatrix.sync.aligned.m8n8.x4.trans.shared.b16 {%0,%1,%2,%3}, [%4];"
        : "=r"(r[0]), "=r"(r[1]), "=r"(r[2]), "=r"(r[3]) : "r"(a));
}
__device__ __forceinline__ void mma16816(float* d, const uint32_t* a, const uint32_t* b) {
    asm volatile(
        "mma.sync.aligned.m16n8k16.row.col.f32.f16.f16.f32 "
        "{%0,%1,%2,%3}, {%4,%5,%6,%7}, {%8,%9}, {%0,%1,%2,%3};"
        : "+f"(d[0]), "+f"(d[1]), "+f"(d[2]), "+f"(d[3])
        : "r"(a[0]), "r"(a[1]), "r"(a[2]), "r"(a[3]), "r"(b[0]), "r"(b[1]));
}
#define CP16(dst, src) \
    asm volatile("cp.async.cg.shared.global [%0], [%1], 16;" :: "r"(dst), "l"(src))
#define CP_COMMIT() asm volatile("cp.async.commit_group;" ::: "memory")
#define CP_WAIT0()  asm volatile("cp.async.wait_group 0;" ::: "memory")

__device__ __forceinline__ uint32_t packh(float a, float b) {
    __half2 h = __floats2half2_rn(a, b);
    return *(uint32_t*)&h;
}
// split two floats into packed fp16 hi + packed fp16 residual
__device__ __forceinline__ void split2h(float a, float b, uint32_t& hi, uint32_t& lo) {
    __half ha = __float2half_rn(a), hb = __float2half_rn(b);
    hi = ((uint32_t)(*(uint16_t*)&hb) << 16) | (uint32_t)(*(uint16_t*)&ha);
    lo = packh(a - __half2float(ha), b - __half2float(hb));
}
// fast exp (FMA pipe), |x| small here
__device__ __forceinline__ float fexp(float x) {
    float t = x * 1.4426950408889634f;
    t = fmaxf(t, -126.0f);
    float n = rintf(t);
    float u = (t - n) * 0.6931471805599453f;
    float p = 1.38888889e-3f;
    p = fmaf(p, u, 8.33333333e-3f);
    p = fmaf(p, u, 4.16666667e-2f);
    p = fmaf(p, u, 1.66666667e-1f);
    p = fmaf(p, u, 0.5f);
    p = fmaf(p, u, 1.0f);
    p = fmaf(p, u, 1.0f);
    float s = __int_as_float(((int)n + 127) << 23);
    return p * s;
}

// ---------------------------------------------------------------------------
// Fused pre-pass: P = x @ (Q/32) -> fp16 hi/lo, AND x -> fp16 (same read of x)
// ---------------------------------------------------------------------------
__global__ __launch_bounds__(256, 2)
void prep_kernel(const float* __restrict__ x, const float* __restrict__ Q) {
    __shared__ float XsT[64 * 64];
    __shared__ float Qs[64 * 64];
    const int t = threadIdx.x;
    const int row0 = blockIdx.x * 64;
    const int ty = t >> 4, tx = t & 15;

    float acc[4][4];
#pragma unroll
    for (int i = 0; i < 4; i++)
#pragma unroll
        for (int j = 0; j < 4; j++) acc[i][j] = 0.f;

    for (int d0 = 0; d0 < DIM; d0 += 64) {
        __syncthreads();
        {
            const int r = t >> 2;
            const int lbase = (t & 3) << 4;
            const float* xp = x + (size_t)(row0 + r) * DIM + d0 + lbase;
            __half* xo = g_xh + (size_t)(row0 + r) * DIM + d0 + lbase;
#pragma unroll
            for (int m = 0; m < 4; m++) {
                float4 v = *(const float4*)(xp + 4 * m);
                // fp16 copy of x
                uint32_t h0 = packh(v.x, v.y), h1 = packh(v.z, v.w);
                *(uint2*)(xo + 4 * m) = make_uint2(h0, h1);
                float vv[4] = {v.x, v.y, v.z, v.w};
#pragma unroll
                for (int k = 0; k < 4; k++) {
                    int l = lbase + 4 * m + k;
                    int phys = (((r >> 2) ^ (l & 15)) << 2) | (r & 3);
                    XsT[l * 64 + phys] = vv[k];
                }
            }
            const int lq = t >> 2;
            const int cb = (t & 3) << 4;
            const float* qp = Q + (size_t)(d0 + lq) * RNK + cb;
#pragma unroll
            for (int m = 0; m < 4; m++)
                *(float4*)&Qs[lq * 64 + cb + 4 * m] = *(const float4*)(qp + 4 * m);
        }
        __syncthreads();
#pragma unroll 4
        for (int l = 0; l < 64; l++) {
            float4 a4 = *(const float4*)&XsT[l * 64 + ((ty ^ (l & 15)) << 2)];
            float4 b4 = *(const float4*)&Qs[l * 64 + (tx << 2)];
            float a[4] = {a4.x, a4.y, a4.z, a4.w};
            float b[4] = {b4.x, b4.y, b4.z, b4.w};
#pragma unroll
            for (int i = 0; i < 4; i++)
#pragma unroll
                for (int j = 0; j < 4; j++)
                    acc[i][j] = fmaf(a[i], b[j], acc[i][j]);
        }
    }
    const float scale = 0.03125f;
#pragma unroll
    for (int i = 0; i < 4; i++) {
        size_t base = (size_t)(row0 + ty * 4 + i) * RNK + tx * 4;
#pragma unroll
        for (int jp = 0; jp < 2; jp++) {
            uint32_t hi, lo;
            split2h(acc[i][2 * jp] * scale, acc[i][2 * jp + 1] * scale, hi, lo);
            *(uint32_t*)&g_P_hi[base + 2 * jp] = hi;
            *(uint32_t*)&g_P_lo[base + 2 * jp] = lo;
        }
    }
}

// ---------------------------------------------------------------------------
// Column sums of x per batch: g_csum[b][d] = sum_s x[b][s][d]   (deterministic)
// ---------------------------------------------------------------------------
__global__ __launch_bounds__(256)
void csum_kernel(const float* __restrict__ x) {
    __shared__ float red[4][64];
    const int t = threadIdx.x;
    const int d = blockIdx.x * 64 + (t & 63);
    const int b = blockIdx.y;
    const int rq = t >> 6;
    const float* xp = x + ((size_t)b * SEQ + (size_t)rq * 1024) * DIM + d;
    float s = 0.f;
#pragma unroll 8
    for (int r = 0; r < 1024; r++) s += xp[(size_t)r * DIM];
    red[rq][t & 63] = s;
    __syncthreads();
    if (rq == 0)
        g_csum[b * DIM + d] = red[0][t] + red[1][t] + red[2][t] + red[3][t];
}

// ---------------------------------------------------------------------------
// Flash attention, fp16 HMMA. grid (32 qtiles, 4 d-slices, 8 batches)
// smem: PQ hi 16K | PKH 2x8K | PKL 2x8K | VH 2x32K = 112K (+pad)
// ---------------------------------------------------------------------------
#define OFF_PQ   0
#define OFF_PKH  16384
#define OFF_PKL  32768
#define OFF_V    49152
#define SMEM_TOTAL 114688

__global__ __launch_bounds__(256, 1)
void attn_kernel(float* __restrict__ out) {
    extern __shared__ char sm[];
    const uint32_t smb = smem_u32(sm);
    const int t = threadIdx.x;
    const int warp = t >> 5, lane = t & 31;
    const int qb = blockIdx.x, z = blockIdx.y, b = blockIdx.z;
    const int q0 = warp * 16;
    const int tg = lane & 3, g = lane >> 2;
    const int i7 = lane & 7, grp = lane >> 3;

    const __half* pk_h = g_P_hi + (size_t)b * SEQ * RNK;
    const __half* pk_l = g_P_lo + (size_t)b * SEQ * RNK;
    const __half* vh_g = g_xh + (size_t)b * SEQ * DIM + (size_t)z * 256;

    // ---- load Pq hi tile [128 q][64 r] into smem (swizzled) ----
#pragma unroll
    for (int m = 0; m < 4; m++) {
        int idx = t + 256 * m;
        int row = idx >> 3, ch = idx & 7;
        size_t src = ((size_t)b * SEQ + (size_t)qb * 128 + row) * RNK + ch * 8;
        uint32_t dst = row * 128 + (((uint32_t)(ch ^ (row & 7))) << 4);
        *(uint4*)(sm + OFF_PQ + dst) = *(const uint4*)(g_P_hi + src);
    }
    // ---- prefetch tile 0 ----
    {
#pragma unroll
        for (int m = 0; m < 2; m++) {
            int idx = t + 256 * m;
            int row = idx >> 3, ch = idx & 7;
            uint32_t dsw = row * 128 + (((uint32_t)(ch ^ (row & 7))) << 4);
            const __half* s1 = pk_h + (size_t)row * RNK + ch * 8;
            const __half* s2 = pk_l + (size_t)row * RNK + ch * 8;
            CP16(smb + OFF_PKH + dsw, s1);
            CP16(smb + OFF_PKL + dsw, s2);
        }
#pragma unroll
        for (int m = 0; m < 8; m++) {
            int idx = t + 256 * m;
            int row = idx >> 5, ch = idx & 31;
            uint32_t dsw = row * 512 + (((uint32_t)(ch ^ (row & 7))) << 4);
            const __half* s1 = vh_g + (size_t)row * DIM + ch * 8;
            CP16(smb + OFF_V + dsw, s1);
        }
        CP_COMMIT();
    }
    __syncthreads();

    // ---- hoist Pq A-fragments into registers (warp-local) ----
    const uint32_t rowA = q0 + i7 + ((grp & 1) << 3);
    const uint32_t cselA = grp >> 1;
    uint32_t aReg[4][4];
#pragma unroll
    for (int kt = 0; kt < 4; kt++) {
        uint32_t aaddr = smb + OFF_PQ + rowA * 128 + ((((kt << 1) + cselA) ^ i7) << 4);
        ldsm4(aReg[kt], aaddr);
    }

    float Y[32][4];
#pragma unroll
    for (int n = 0; n < 32; n++)
#pragma unroll
        for (int e = 0; e < 4; e++) Y[n][e] = 0.f;
    float Ll = 0.f, Lh = 0.f;

    const uint32_t rowB = i7 + ((grp >> 1) << 3);
    const uint32_t cselB = grp & 1;
    const uint32_t rowV = i7 + ((grp & 1) << 3);
    const uint32_t cselV = grp >> 1;

    for (int it = 0; it < NIT; it++) {
        const int buf = it & 1;
        CP_WAIT0();
        __syncthreads();     // tile ready; all warps done with buf^1

        // ---- prefetch tile it+1 into buf^1 (overlaps compute) ----
        if (it + 1 < NIT) {
            const int k0n = (it + 1) * KB;
            const uint32_t bo = (buf ^ 1);
#pragma unroll
            for (int m = 0; m < 2; m++) {
                int idx = t + 256 * m;
                int row = idx >> 3, ch = idx & 7;
                uint32_t dsw = row * 128 + (((uint32_t)(ch ^ (row & 7))) << 4);
                const __half* s1 = pk_h + (size_t)(k0n + row) * RNK + ch * 8;
                const __half* s2 = pk_l + (size_t)(k0n + row) * RNK + ch * 8;
                CP16(smb + OFF_PKH + bo * 8192 + dsw, s1);
                CP16(smb + OFF_PKL + bo * 8192 + dsw, s2);
            }
#pragma unroll
            for (int m = 0; m < 8; m++) {
                int idx = t + 256 * m;
                int row = idx >> 5, ch = idx & 31;
                uint32_t dsw = row * 512 + (((uint32_t)(ch ^ (row & 7))) << 4);
                const __half* s1 = vh_g + (size_t)(k0n + row) * DIM + ch * 8;
                CP16(smb + OFF_V + bo * 32768 + dsw, s1);
            }
            CP_COMMIT();
        }

        // ---- QK^T (2 combos: qh*kh + qh*kl) ----
        float S[8][4];
#pragma unroll
        for (int n = 0; n < 8; n++)
#pragma unroll
            for (int e = 0; e < 4; e++) S[n][e] = 0.f;

        const uint32_t pkBase = smb + OFF_PKH + buf * 8192;
#pragma unroll
        for (int kt = 0; kt < 4; kt++) {
#pragma unroll
            for (int np = 0; np < 4; np++) {
                uint32_t bh[4], bl[4];
                uint32_t baddr = pkBase + ((np << 4) + rowB) * 128
                               + ((((kt << 1) + cselB) ^ i7) << 4);
                ldsm4(bh, baddr);
                ldsm4(bl, baddr + (OFF_PKL - OFF_PKH));
                mma16816(S[2 * np],     aReg[kt], bh + 0);
                mma16816(S[2 * np],     aReg[kt], bl + 0);
                mma16816(S[2 * np + 1], aReg[kt], bh + 2);
                mma16816(S[2 * np + 1], aReg[kt], bl + 2);
            }
        }

        // ---- softmax probs (no max-shift; tiny logits); mean-shift for PV ----
        float rl = 0.f, rh = 0.f;
#pragma unroll
        for (int n = 0; n < 8; n++) {
            S[n][0] = fexp(S[n][0]);
            S[n][1] = fexp(S[n][1]);
            S[n][2] = fexp(S[n][2]);
            S[n][3] = fexp(S[n][3]);
            rl += S[n][0] + S[n][1];
            rh += S[n][2] + S[n][3];
        }
        rl += __shfl_xor_sync(0xffffffffu, rl, 1);
        rl += __shfl_xor_sync(0xffffffffu, rl, 2);
        rh += __shfl_xor_sync(0xffffffffu, rh, 1);
        rh += __shfl_xor_sync(0xffffffffu, rh, 2);
        Ll += rl;
        Lh += rh;

        // pack (p - 1) into fp16 A-fragments
        uint32_t Ph[4][4];
#pragma unroll
        for (int kt = 0; kt < 4; kt++) {
            int n0 = 2 * kt;
            Ph[kt][0] = packh(S[n0][0] - 1.f,     S[n0][1] - 1.f);
            Ph[kt][1] = packh(S[n0][2] - 1.f,     S[n0][3] - 1.f);
            Ph[kt][2] = packh(S[n0 + 1][0] - 1.f, S[n0 + 1][1] - 1.f);
            Ph[kt][3] = packh(S[n0 + 1][2] - 1.f, S[n0 + 1][3] - 1.f);
        }

        // ---- PV: Y += (P-1) @ V (single combo) ----
        const uint32_t vBase = smb + OFF_V + buf * 32768;
#pragma unroll
        for (int kt = 0; kt < 4; kt++) {
            uint32_t vrow = vBase + ((kt << 4) + rowV) * 512;
#pragma unroll
            for (int np = 0; np < 16; np++) {
                uint32_t bh[4];
                ldsm4t(bh, vrow + ((((np << 1) + cselV) ^ i7) << 4));
                mma16816(Y[2 * np],     Ph[kt], bh + 0);
                mma16816(Y[2 * np + 1], Ph[kt], bh + 2);
            }
        }
    }

    // ---- epilogue: y = (csum + Ydot) / l ----
    const float il = 1.0f / Ll;
    const float ih = 1.0f / Lh;
    const int rlo = qb * 128 + q0 + g;
    const float* cs_base = g_csum + b * DIM + z * 256 + 2 * tg;
    float* o_lo = out + ((size_t)b * SEQ + rlo) * DIM + (size_t)z * 256 + 2 * tg;
    float* o_hi = o_lo + (size_t)8 * DIM;
#pragma unroll
    for (int n = 0; n < 32; n++) {
        float2 cs = *(const float2*)(cs_base + 8 * n);
        float2 p;
        p.x = (Y[n][0] + cs.x) * il; p.y = (Y[n][1] + cs.y) * il;
        *(float2*)(o_lo + 8 * n) = p;
        p.x = (Y[n][2] + cs.x) * ih; p.y = (Y[n][3] + cs.y) * ih;
        *(float2*)(o_hi + 8 * n) = p;
    }
}

// ---------------------------------------------------------------------------
extern "C" void kernel_launch(void* const* d_in, const int* in_sizes, int n_in,
                              void* d_out, int out_size) {
    const float* x = (const float*)d_in[0];
    const float* Q = (const float*)d_in[1];
    float* out = (float*)d_out;

    cudaFuncSetAttribute(attn_kernel, cudaFuncAttributeMaxDynamicSharedMemorySize,
                         SMEM_TOTAL);

    prep_kernel<<<(BATCH * SEQ) / 64, 256>>>(x, Q);
    csum_kernel<<<dim3(DIM / 64, BATCH), 256>>>(x);
    attn_kernel<<<dim3(SEQ / 128, DIM / 256, BATCH), 256, SMEM_TOTAL>>>(out);
}

// round 5
// speedup vs baseline: 7.4093x; 1.2122x over previous
#include <cuda_runtime.h>
#include <cuda_fp16.h>
#include <cstdint>

#define BATCH 8
#define SEQ   4096
#define DIM   1024
#define RNK   64
#define KB    64
#define NIT   (SEQ/KB)

// ---------------- global scratch ----------------
__device__ __align__(16) __half g_P[BATCH * SEQ * RNK];
__device__ __align__(16) __half g_xh[(size_t)BATCH * SEQ * DIM];
__device__ __align__(16) __half g_Qt[RNK * DIM];          // Q^T / 32, fp16
__device__ __align__(16) float  g_csum[BATCH * DIM];

// ---------------- helpers ----------------
__device__ __forceinline__ uint32_t smem_u32(const void* p) {
    uint32_t a;
    asm("{ .reg .u64 t; cvta.to.shared.u64 t, %1; cvt.u32.u64 %0, t; }" : "=r"(a) : "l"(p));
    return a;
}
__device__ __forceinline__ void ldsm4(uint32_t* r, uint32_t a) {
    asm volatile("ldmatrix.sync.aligned.m8n8.x4.shared.b16 {%0,%1,%2,%3}, [%4];"
        : "=r"(r[0]), "=r"(r[1]), "=r"(r[2]), "=r"(r[3]) : "r"(a));
}
__device__ __forceinline__ void ldsm4t(uint32_t* r, uint32_t a) {
    asm volatile("ldmatrix.sync.aligned.m8n8.x4.trans.shared.b16 {%0,%1,%2,%3}, [%4];"
        : "=r"(r[0]), "=r"(r[1]), "=r"(r[2]), "=r"(r[3]) : "r"(a));
}
__device__ __forceinline__ void mma16816(float* d, const uint32_t* a, const uint32_t* b) {
    asm volatile(
        "mma.sync.aligned.m16n8k16.row.col.f32.f16.f16.f32 "
        "{%0,%1,%2,%3}, {%4,%5,%6,%7}, {%8,%9}, {%0,%1,%2,%3};"
        : "+f"(d[0]), "+f"(d[1]), "+f"(d[2]), "+f"(d[3])
        : "r"(a[0]), "r"(a[1]), "r"(a[2]), "r"(a[3]), "r"(b[0]), "r"(b[1]));
}
#define CP16(dst, src) \
    asm volatile("cp.async.cg.shared.global [%0], [%1], 16;" :: "r"(dst), "l"(src))
#define CP_COMMIT() asm volatile("cp.async.commit_group;" ::: "memory")
#define CP_WAIT0()  asm volatile("cp.async.wait_group 0;" ::: "memory")

__device__ __forceinline__ uint32_t packh(float a, float b) {
    __half2 h = __floats2half2_rn(a, b);
    return *(uint32_t*)&h;
}
// fast exp (FMA pipe), |x| small here
__device__ __forceinline__ float fexp(float x) {
    float t = x * 1.4426950408889634f;
    t = fmaxf(t, -126.0f);
    float n = rintf(t);
    float u = (t - n) * 0.6931471805599453f;
    float p = 1.38888889e-3f;
    p = fmaf(p, u, 8.33333333e-3f);
    p = fmaf(p, u, 4.16666667e-2f);
    p = fmaf(p, u, 1.66666667e-1f);
    p = fmaf(p, u, 0.5f);
    p = fmaf(p, u, 1.0f);
    p = fmaf(p, u, 1.0f);
    float s = __int_as_float(((int)n + 127) << 23);
    return p * s;
}

// ---------------------------------------------------------------------------
// cvt: x fp32 -> fp16 (streaming)
// ---------------------------------------------------------------------------
__global__ __launch_bounds__(256)
void cvt_kernel(const float* __restrict__ x) {
    size_t idx = (size_t)blockIdx.x * 256 + threadIdx.x;   // float4 index
    float4 v = ((const float4*)x)[idx];
    ((uint2*)g_xh)[idx] = make_uint2(packh(v.x, v.y), packh(v.z, v.w));
}

// ---------------------------------------------------------------------------
// qprep: Q [1024 k][64 n] fp32 -> g_Qt [64 n][1024 k] fp16, scaled by 1/32
// ---------------------------------------------------------------------------
__global__ __launch_bounds__(256)
void qprep_kernel(const float* __restrict__ Q) {
    __shared__ float ts[64][65];
    const int t = threadIdx.x;
    const int k0 = blockIdx.x * 64;
    const int r = t >> 2, cb = (t & 3) << 4;
    const float* qp = Q + (size_t)(k0 + r) * RNK + cb;
#pragma unroll
    for (int m = 0; m < 4; m++) {
        float4 v = *(const float4*)(qp + 4 * m);
        ts[r][cb + 4 * m + 0] = v.x * 0.03125f;
        ts[r][cb + 4 * m + 1] = v.y * 0.03125f;
        ts[r][cb + 4 * m + 2] = v.z * 0.03125f;
        ts[r][cb + 4 * m + 3] = v.w * 0.03125f;
    }
    __syncthreads();
    // n = r, k-chunk cb..cb+15
    __half* o = g_Qt + (size_t)r * DIM + k0 + cb;
#pragma unroll
    for (int m = 0; m < 2; m++) {
        uint32_t w[4];
#pragma unroll
        for (int p = 0; p < 4; p++)
            w[p] = packh(ts[cb + 8 * m + 2 * p][r], ts[cb + 8 * m + 2 * p + 1][r]);
        *(uint4*)(o + 8 * m) = make_uint4(w[0], w[1], w[2], w[3]);
    }
}

// ---------------------------------------------------------------------------
// projH: P = x_h @ Qt^T via HMMA. grid 256 CTAs x 128 rows. smem 48KB.
// ---------------------------------------------------------------------------
#define POFF_X 0          // 2 x 16384
#define POFF_Q 32768      // 2 x 8192
#define PSM_TOTAL 49152

__global__ __launch_bounds__(256, 2)
void projH_kernel() {
    extern __shared__ char sm[];
    const uint32_t smb = smem_u32(sm);
    const int t = threadIdx.x;
    const int warp = t >> 5, lane = t & 31;
    const int row0 = blockIdx.x * 128;
    const int q0 = warp * 16;
    const int tg = lane & 3, g = lane >> 2;
    const int i7 = lane & 7, grp = lane >> 3;

    // prefetch chunk 0
    {
#pragma unroll
        for (int m = 0; m < 4; m++) {
            int idx = t + 256 * m;
            int row = idx >> 3, ch = idx & 7;
            uint32_t dsw = row * 128 + (((uint32_t)(ch ^ (row & 7))) << 4);
            CP16(smb + POFF_X + dsw, g_xh + (size_t)(row0 + row) * DIM + ch * 8);
        }
#pragma unroll
        for (int m = 0; m < 2; m++) {
            int idx = t + 256 * m;
            int row = idx >> 3, ch = idx & 7;
            uint32_t dsw = row * 128 + (((uint32_t)(ch ^ (row & 7))) << 4);
            CP16(smb + POFF_Q + dsw, g_Qt + (size_t)row * DIM + ch * 8);
        }
        CP_COMMIT();
    }

    const uint32_t rowA = q0 + i7 + ((grp & 1) << 3);
    const uint32_t cselA = grp >> 1;
    const uint32_t rowB = i7 + ((grp >> 1) << 3);
    const uint32_t cselB = grp & 1;

    float S[8][4];
#pragma unroll
    for (int n = 0; n < 8; n++)
#pragma unroll
        for (int e = 0; e < 4; e++) S[n][e] = 0.f;

    for (int c = 0; c < 16; c++) {
        const int buf = c & 1;
        CP_WAIT0();
        __syncthreads();
        if (c + 1 < 16) {
            const int kc = (c + 1) * 64;
            const int bo = buf ^ 1;
#pragma unroll
            for (int m = 0; m < 4; m++) {
                int idx = t + 256 * m;
                int row = idx >> 3, ch = idx & 7;
                uint32_t dsw = row * 128 + (((uint32_t)(ch ^ (row & 7))) << 4);
                CP16(smb + POFF_X + bo * 16384 + dsw,
                     g_xh + (size_t)(row0 + row) * DIM + kc + ch * 8);
            }
#pragma unroll
            for (int m = 0; m < 2; m++) {
                int idx = t + 256 * m;
                int row = idx >> 3, ch = idx & 7;
                uint32_t dsw = row * 128 + (((uint32_t)(ch ^ (row & 7))) << 4);
                CP16(smb + POFF_Q + bo * 8192 + dsw,
                     g_Qt + (size_t)row * DIM + kc + ch * 8);
            }
            CP_COMMIT();
        }
        const uint32_t xb = smb + POFF_X + buf * 16384;
        const uint32_t qb = smb + POFF_Q + buf * 8192;
#pragma unroll
        for (int kt = 0; kt < 4; kt++) {
            uint32_t ah[4];
            ldsm4(ah, xb + rowA * 128 + ((((kt << 1) + cselA) ^ i7) << 4));
#pragma unroll
            for (int np = 0; np < 4; np++) {
                uint32_t bh[4];
                ldsm4(bh, qb + ((np << 4) + rowB) * 128
                          + ((((kt << 1) + cselB) ^ i7) << 4));
                mma16816(S[2 * np],     ah, bh + 0);
                mma16816(S[2 * np + 1], ah, bh + 2);
            }
        }
        __syncthreads();
    }

    // epilogue: store P fp16
    const int row = row0 + q0 + g;
#pragma unroll
    for (int j = 0; j < 8; j++) {
        const int nb = (j >> 1) * 16 + (j & 1) * 8;
        *(uint32_t*)&g_P[(size_t)row * RNK + nb + 2 * tg] = packh(S[j][0], S[j][1]);
        *(uint32_t*)&g_P[(size_t)(row + 8) * RNK + nb + 2 * tg] = packh(S[j][2], S[j][3]);
    }
}

// ---------------------------------------------------------------------------
// Column sums of x per batch (deterministic, fp32)
// ---------------------------------------------------------------------------
__global__ __launch_bounds__(256)
void csum_kernel(const float* __restrict__ x) {
    __shared__ float red[4][64];
    const int t = threadIdx.x;
    const int d = blockIdx.x * 64 + (t & 63);
    const int b = blockIdx.y;
    const int rq = t >> 6;
    const float* xp = x + ((size_t)b * SEQ + (size_t)rq * 1024) * DIM + d;
    float s = 0.f;
#pragma unroll 8
    for (int r = 0; r < 1024; r++) s += xp[(size_t)r * DIM];
    red[rq][t & 63] = s;
    __syncthreads();
    if (rq == 0)
        g_csum[b * DIM + d] = red[0][t] + red[1][t] + red[2][t] + red[3][t];
}

// ---------------------------------------------------------------------------
// Flash attention, fp16 HMMA. grid (32 qtiles, 4 d-slices, 8 batches)
// smem: PQ 16K | PK 2x8K | V 2x32K = 96K
// ---------------------------------------------------------------------------
#define OFF_PQ   0
#define OFF_PK   16384
#define OFF_V    32768
#define SMEM_TOTAL 98304

__global__ __launch_bounds__(256, 1)
void attn_kernel(float* __restrict__ out) {
    extern __shared__ char sm[];
    const uint32_t smb = smem_u32(sm);
    const int t = threadIdx.x;
    const int warp = t >> 5, lane = t & 31;
    const int qb = blockIdx.x, z = blockIdx.y, b = blockIdx.z;
    const int q0 = warp * 16;
    const int tg = lane & 3, g = lane >> 2;
    const int i7 = lane & 7, grp = lane >> 3;

    const __half* pk_g = g_P + (size_t)b * SEQ * RNK;
    const __half* vh_g = g_xh + (size_t)b * SEQ * DIM + (size_t)z * 256;

    // ---- load Pq tile [128 q][64 r] into smem (swizzled) ----
#pragma unroll
    for (int m = 0; m < 4; m++) {
        int idx = t + 256 * m;
        int row = idx >> 3, ch = idx & 7;
        size_t src = ((size_t)b * SEQ + (size_t)qb * 128 + row) * RNK + ch * 8;
        uint32_t dst = row * 128 + (((uint32_t)(ch ^ (row & 7))) << 4);
        *(uint4*)(sm + OFF_PQ + dst) = *(const uint4*)(g_P + src);
    }
    // ---- prefetch tile 0 ----
    {
#pragma unroll
        for (int m = 0; m < 2; m++) {
            int idx = t + 256 * m;
            int row = idx >> 3, ch = idx & 7;
            uint32_t dsw = row * 128 + (((uint32_t)(ch ^ (row & 7))) << 4);
            CP16(smb + OFF_PK + dsw, pk_g + (size_t)row * RNK + ch * 8);
        }
#pragma unroll
        for (int m = 0; m < 8; m++) {
            int idx = t + 256 * m;
            int row = idx >> 5, ch = idx & 31;
            uint32_t dsw = row * 512 + (((uint32_t)(ch ^ (row & 7))) << 4);
            CP16(smb + OFF_V + dsw, vh_g + (size_t)row * DIM + ch * 8);
        }
        CP_COMMIT();
    }
    __syncthreads();

    // ---- hoist Pq A-fragments into registers ----
    const uint32_t rowA = q0 + i7 + ((grp & 1) << 3);
    const uint32_t cselA = grp >> 1;
    uint32_t aReg[4][4];
#pragma unroll
    for (int kt = 0; kt < 4; kt++)
        ldsm4(aReg[kt], smb + OFF_PQ + rowA * 128 + ((((kt << 1) + cselA) ^ i7) << 4));

    float Y[32][4];
#pragma unroll
    for (int n = 0; n < 32; n++)
#pragma unroll
        for (int e = 0; e < 4; e++) Y[n][e] = 0.f;
    float Ll = 0.f, Lh = 0.f;

    const uint32_t rowB = i7 + ((grp >> 1) << 3);
    const uint32_t cselB = grp & 1;
    const uint32_t rowV = i7 + ((grp & 1) << 3);
    const uint32_t cselV = grp >> 1;

    for (int it = 0; it < NIT; it++) {
        const int buf = it & 1;
        CP_WAIT0();
        __syncthreads();

        // prefetch tile it+1 (overlaps compute)
        if (it + 1 < NIT) {
            const int k0n = (it + 1) * KB;
            const int bo = buf ^ 1;
#pragma unroll
            for (int m = 0; m < 2; m++) {
                int idx = t + 256 * m;
                int row = idx >> 3, ch = idx & 7;
                uint32_t dsw = row * 128 + (((uint32_t)(ch ^ (row & 7))) << 4);
                CP16(smb + OFF_PK + bo * 8192 + dsw,
                     pk_g + (size_t)(k0n + row) * RNK + ch * 8);
            }
#pragma unroll
            for (int m = 0; m < 8; m++) {
                int idx = t + 256 * m;
                int row = idx >> 5, ch = idx & 31;
                uint32_t dsw = row * 512 + (((uint32_t)(ch ^ (row & 7))) << 4);
                CP16(smb + OFF_V + bo * 32768 + dsw,
                     vh_g + (size_t)(k0n + row) * DIM + ch * 8);
            }
            CP_COMMIT();
        }

        // ---- QK^T (single combo) ----
        float S[8][4];
#pragma unroll
        for (int n = 0; n < 8; n++)
#pragma unroll
            for (int e = 0; e < 4; e++) S[n][e] = 0.f;

        const uint32_t pkBase = smb + OFF_PK + buf * 8192;
#pragma unroll
        for (int kt = 0; kt < 4; kt++) {
#pragma unroll
            for (int np = 0; np < 4; np++) {
                uint32_t bh[4];
                ldsm4(bh, pkBase + ((np << 4) + rowB) * 128
                          + ((((kt << 1) + cselB) ^ i7) << 4));
                mma16816(S[2 * np],     aReg[kt], bh + 0);
                mma16816(S[2 * np + 1], aReg[kt], bh + 2);
            }
        }

        // ---- softmax probs; mean-shift for PV ----
        float rl = 0.f, rh = 0.f;
#pragma unroll
        for (int n = 0; n < 8; n++) {
            S[n][0] = fexp(S[n][0]);
            S[n][1] = fexp(S[n][1]);
            S[n][2] = fexp(S[n][2]);
            S[n][3] = fexp(S[n][3]);
            rl += S[n][0] + S[n][1];
            rh += S[n][2] + S[n][3];
        }
        rl += __shfl_xor_sync(0xffffffffu, rl, 1);
        rl += __shfl_xor_sync(0xffffffffu, rl, 2);
        rh += __shfl_xor_sync(0xffffffffu, rh, 1);
        rh += __shfl_xor_sync(0xffffffffu, rh, 2);
        Ll += rl;
        Lh += rh;

        uint32_t Ph[4][4];
#pragma unroll
        for (int kt = 0; kt < 4; kt++) {
            int n0 = 2 * kt;
            Ph[kt][0] = packh(S[n0][0] - 1.f,     S[n0][1] - 1.f);
            Ph[kt][1] = packh(S[n0][2] - 1.f,     S[n0][3] - 1.f);
            Ph[kt][2] = packh(S[n0 + 1][0] - 1.f, S[n0 + 1][1] - 1.f);
            Ph[kt][3] = packh(S[n0 + 1][2] - 1.f, S[n0 + 1][3] - 1.f);
        }

        // ---- PV: Y += (P-1) @ V ----
        const uint32_t vBase = smb + OFF_V + buf * 32768;
#pragma unroll
        for (int kt = 0; kt < 4; kt++) {
            uint32_t vrow = vBase + ((kt << 4) + rowV) * 512;
#pragma unroll
            for (int np = 0; np < 16; np++) {
                uint32_t bh[4];
                ldsm4t(bh, vrow + ((((np << 1) + cselV) ^ i7) << 4));
                mma16816(Y[2 * np],     Ph[kt], bh + 0);
                mma16816(Y[2 * np + 1], Ph[kt], bh + 2);
            }
        }
    }

    // ---- epilogue: y = (csum + Ydot) / l ----
    const float il = 1.0f / Ll;
    const float ih = 1.0f / Lh;
    const int rlo = qb * 128 + q0 + g;
    const float* cs_base = g_csum + b * DIM + z * 256 + 2 * tg;
    float* o_lo = out + ((size_t)b * SEQ + rlo) * DIM + (size_t)z * 256 + 2 * tg;
    float* o_hi = o_lo + (size_t)8 * DIM;
#pragma unroll
    for (int n = 0; n < 32; n++) {
        float2 cs = *(const float2*)(cs_base + 8 * n);
        float2 p;
        p.x = (Y[n][0] + cs.x) * il; p.y = (Y[n][1] + cs.y) * il;
        *(float2*)(o_lo + 8 * n) = p;
        p.x = (Y[n][2] + cs.x) * ih; p.y = (Y[n][3] + cs.y) * ih;
        *(float2*)(o_hi + 8 * n) = p;
    }
}

// ---------------------------------------------------------------------------
extern "C" void kernel_launch(void* const* d_in, const int* in_sizes, int n_in,
                              void* d_out, int out_size) {
    const float* x = (const float*)d_in[0];
    const float* Q = (const float*)d_in[1];
    float* out = (float*)d_out;

    cudaFuncSetAttribute(attn_kernel, cudaFuncAttributeMaxDynamicSharedMemorySize,
                         SMEM_TOTAL);
    cudaFuncSetAttribute(projH_kernel, cudaFuncAttributeMaxDynamicSharedMemorySize,
                         PSM_TOTAL);

    cvt_kernel<<<(size_t)BATCH * SEQ * DIM / 4 / 256, 256>>>(x);
    qprep_kernel<<<DIM / 64, 256>>>(Q);
    projH_kernel<<<BATCH * SEQ / 128, 256, PSM_TOTAL>>>();
    csum_kernel<<<dim3(DIM / 64, BATCH), 256>>>(x);
    attn_kernel<<<dim3(SEQ / 128, DIM / 256, BATCH), 256, SMEM_TOTAL>>>(out);
}

// round 6
// speedup vs baseline: 9.4908x; 1.2809x over previous
#include <cuda_runtime.h>
#include <cuda_fp16.h>
#include <cstdint>

#define BATCH 8
#define SEQ   4096
#define DIM   1024
#define RNK   64
#define KB    64
#define NIT   (SEQ/KB)

// ---------------- global scratch ----------------
__device__ __align__(16) __half g_P[BATCH * SEQ * RNK];
__device__ __align__(16) __half g_xh[(size_t)BATCH * SEQ * DIM];
__device__ __align__(16) __half g_Qt[RNK * DIM];          // Q^T * sqrt(log2e)/32, fp16
__device__ __align__(16) float  g_csum[BATCH * DIM];
__device__ __align__(16) float  g_cpart[8][BATCH * DIM];

// ---------------- helpers ----------------
__device__ __forceinline__ uint32_t smem_u32(const void* p) {
    uint32_t a;
    asm("{ .reg .u64 t; cvta.to.shared.u64 t, %1; cvt.u32.u64 %0, t; }" : "=r"(a) : "l"(p));
    return a;
}
__device__ __forceinline__ void ldsm4(uint32_t* r, uint32_t a) {
    asm volatile("ldmatrix.sync.aligned.m8n8.x4.shared.b16 {%0,%1,%2,%3}, [%4];"
        : "=r"(r[0]), "=r"(r[1]), "=r"(r[2]), "=r"(r[3]) : "r"(a));
}
__device__ __forceinline__ void ldsm4t(uint32_t* r, uint32_t a) {
    asm volatile("ldmatrix.sync.aligned.m8n8.x4.trans.shared.b16 {%0,%1,%2,%3}, [%4];"
        : "=r"(r[0]), "=r"(r[1]), "=r"(r[2]), "=r"(r[3]) : "r"(a));
}
__device__ __forceinline__ void mma16816(float* d, const uint32_t* a, const uint32_t* b) {
    asm volatile(
        "mma.sync.aligned.m16n8k16.row.col.f32.f16.f16.f32 "
        "{%0,%1,%2,%3}, {%4,%5,%6,%7}, {%8,%9}, {%0,%1,%2,%3};"
        : "+f"(d[0]), "+f"(d[1]), "+f"(d[2]), "+f"(d[3])
        : "r"(a[0]), "r"(a[1]), "r"(a[2]), "r"(a[3]), "r"(b[0]), "r"(b[1]));
}
#define CP16(dst, src) \
    asm volatile("cp.async.cg.shared.global [%0], [%1], 16;" :: "r"(dst), "l"(src))
#define CP_COMMIT() asm volatile("cp.async.commit_group;" ::: "memory")
#define CP_WAIT0()  asm volatile("cp.async.wait_group 0;" ::: "memory")

__device__ __forceinline__ uint32_t packh(float a, float b) {
    __half2 h = __floats2half2_rn(a, b);
    return *(uint32_t*)&h;
}
// exp with log2e pre-folded into the logits: p = 2^s  (single MUFU op)
__device__ __forceinline__ float ex2(float s) {
    float p;
    asm("ex2.approx.f32 %0, %1;" : "=f"(p) : "f"(s));
    return p;
}

// ---------------------------------------------------------------------------
// cvt: x fp32 -> fp16 (streaming)
// ---------------------------------------------------------------------------
__global__ __launch_bounds__(256)
void cvt_kernel(const float* __restrict__ x) {
    size_t idx = (size_t)blockIdx.x * 256 + threadIdx.x;   // float4 index
    float4 v = ((const float4*)x)[idx];
    ((uint2*)g_xh)[idx] = make_uint2(packh(v.x, v.y), packh(v.z, v.w));
}

// ---------------------------------------------------------------------------
// qprep: Q [1024 k][64 n] fp32 -> g_Qt [64 n][1024 k] fp16, scaled by
// sqrt(log2(e))/32 so that logits come out pre-multiplied by log2(e).
// ---------------------------------------------------------------------------
__global__ __launch_bounds__(256)
void qprep_kernel(const float* __restrict__ Q) {
    __shared__ float ts[64][65];
    const int t = threadIdx.x;
    const int k0 = blockIdx.x * 64;
    const int r = t >> 2, cb = (t & 3) << 4;
    const float SC = 0.037535075274576556f;   // sqrt(log2 e) / 32
    const float* qp = Q + (size_t)(k0 + r) * RNK + cb;
#pragma unroll
    for (int m = 0; m < 4; m++) {
        float4 v = *(const float4*)(qp + 4 * m);
        ts[r][cb + 4 * m + 0] = v.x * SC;
        ts[r][cb + 4 * m + 1] = v.y * SC;
        ts[r][cb + 4 * m + 2] = v.z * SC;
        ts[r][cb + 4 * m + 3] = v.w * SC;
    }
    __syncthreads();
    __half* o = g_Qt + (size_t)r * DIM + k0 + cb;
#pragma unroll
    for (int m = 0; m < 2; m++) {
        uint32_t w[4];
#pragma unroll
        for (int p = 0; p < 4; p++)
            w[p] = packh(ts[cb + 8 * m + 2 * p][r], ts[cb + 8 * m + 2 * p + 1][r]);
        *(uint4*)(o + 8 * m) = make_uint4(w[0], w[1], w[2], w[3]);
    }
}

// ---------------------------------------------------------------------------
// projH: P = x_h @ Qt^T via HMMA. grid 256 CTAs x 128 rows. smem 48KB.
// ---------------------------------------------------------------------------
#define POFF_X 0          // 2 x 16384
#define POFF_Q 32768      // 2 x 8192
#define PSM_TOTAL 49152

__global__ __launch_bounds__(256, 2)
void projH_kernel() {
    extern __shared__ char sm[];
    const uint32_t smb = smem_u32(sm);
    const int t = threadIdx.x;
    const int warp = t >> 5, lane = t & 31;
    const int row0 = blockIdx.x * 128;
    const int q0 = warp * 16;
    const int tg = lane & 3, g = lane >> 2;
    const int i7 = lane & 7, grp = lane >> 3;

    // prefetch chunk 0
    {
#pragma unroll
        for (int m = 0; m < 4; m++) {
            int idx = t + 256 * m;
            int row = idx >> 3, ch = idx & 7;
            uint32_t dsw = row * 128 + (((uint32_t)(ch ^ (row & 7))) << 4);
            CP16(smb + POFF_X + dsw, g_xh + (size_t)(row0 + row) * DIM + ch * 8);
        }
#pragma unroll
        for (int m = 0; m < 2; m++) {
            int idx = t + 256 * m;
            int row = idx >> 3, ch = idx & 7;
            uint32_t dsw = row * 128 + (((uint32_t)(ch ^ (row & 7))) << 4);
            CP16(smb + POFF_Q + dsw, g_Qt + (size_t)row * DIM + ch * 8);
        }
        CP_COMMIT();
    }

    const uint32_t rowA = q0 + i7 + ((grp & 1) << 3);
    const uint32_t cselA = grp >> 1;
    const uint32_t rowB = i7 + ((grp >> 1) << 3);
    const uint32_t cselB = grp & 1;

    float S[8][4];
#pragma unroll
    for (int n = 0; n < 8; n++)
#pragma unroll
        for (int e = 0; e < 4; e++) S[n][e] = 0.f;

    for (int c = 0; c < 16; c++) {
        const int buf = c & 1;
        CP_WAIT0();
        __syncthreads();
        if (c + 1 < 16) {
            const int kc = (c + 1) * 64;
            const int bo = buf ^ 1;
#pragma unroll
            for (int m = 0; m < 4; m++) {
                int idx = t + 256 * m;
                int row = idx >> 3, ch = idx & 7;
                uint32_t dsw = row * 128 + (((uint32_t)(ch ^ (row & 7))) << 4);
                CP16(smb + POFF_X + bo * 16384 + dsw,
                     g_xh + (size_t)(row0 + row) * DIM + kc + ch * 8);
            }
#pragma unroll
            for (int m = 0; m < 2; m++) {
                int idx = t + 256 * m;
                int row = idx >> 3, ch = idx & 7;
                uint32_t dsw = row * 128 + (((uint32_t)(ch ^ (row & 7))) << 4);
                CP16(smb + POFF_Q + bo * 8192 + dsw,
                     g_Qt + (size_t)row * DIM + kc + ch * 8);
            }
            CP_COMMIT();
        }
        const uint32_t xb = smb + POFF_X + buf * 16384;
        const uint32_t qb = smb + POFF_Q + buf * 8192;
#pragma unroll
        for (int kt = 0; kt < 4; kt++) {
            uint32_t ah[4];
            ldsm4(ah, xb + rowA * 128 + ((((kt << 1) + cselA) ^ i7) << 4));
#pragma unroll
            for (int np = 0; np < 4; np++) {
                uint32_t bh[4];
                ldsm4(bh, qb + ((np << 4) + rowB) * 128
                          + ((((kt << 1) + cselB) ^ i7) << 4));
                mma16816(S[2 * np],     ah, bh + 0);
                mma16816(S[2 * np + 1], ah, bh + 2);
            }
        }
        __syncthreads();
    }

    // epilogue: store P fp16
    const int row = row0 + q0 + g;
#pragma unroll
    for (int j = 0; j < 8; j++) {
        const int nb = (j >> 1) * 16 + (j & 1) * 8;
        *(uint32_t*)&g_P[(size_t)row * RNK + nb + 2 * tg] = packh(S[j][0], S[j][1]);
        *(uint32_t*)&g_P[(size_t)(row + 8) * RNK + nb + 2 * tg] = packh(S[j][2], S[j][3]);
    }
}

// ---------------------------------------------------------------------------
// Column sums of x per batch, 2-stage deterministic.
// Stage 1: grid (DIM/64, BATCH, 8), each block sums a 512-row chunk.
// ---------------------------------------------------------------------------
__global__ __launch_bounds__(256)
void csum1_kernel(const float* __restrict__ x) {
    __shared__ float red[4][64];
    const int t = threadIdx.x;
    const int d = blockIdx.x * 64 + (t & 63);
    const int b = blockIdx.y;
    const int c = blockIdx.z;
    const int rq = t >> 6;
    const float* xp = x + ((size_t)b * SEQ + (size_t)c * 512 + (size_t)rq * 128) * DIM + d;
    float s = 0.f;
#pragma unroll 8
    for (int r = 0; r < 128; r++) s += xp[(size_t)r * DIM];
    red[rq][t & 63] = s;
    __syncthreads();
    if (rq == 0)
        g_cpart[c][b * DIM + d] = red[0][t] + red[1][t] + red[2][t] + red[3][t];
}
__global__ __launch_bounds__(256)
void csum2_kernel() {
    const int idx = blockIdx.x * 256 + threadIdx.x;
    float s = 0.f;
#pragma unroll
    for (int c = 0; c < 8; c++) s += g_cpart[c][idx];
    g_csum[idx] = s;
}

// ---------------------------------------------------------------------------
// Flash attention, fp16 HMMA. grid (32 qtiles, 4 d-slices, 8 batches)
// smem: PQ 16K | PK 2x8K | V 2x32K = 96K
// ---------------------------------------------------------------------------
#define OFF_PQ   0
#define OFF_PK   16384
#define OFF_V    32768
#define SMEM_TOTAL 98304

__global__ __launch_bounds__(256, 1)
void attn_kernel(float* __restrict__ out) {
    extern __shared__ char sm[];
    const uint32_t smb = smem_u32(sm);
    const int t = threadIdx.x;
    const int warp = t >> 5, lane = t & 31;
    const int qb = blockIdx.x, z = blockIdx.y, b = blockIdx.z;
    const int q0 = warp * 16;
    const int tg = lane & 3, g = lane >> 2;
    const int i7 = lane & 7, grp = lane >> 3;

    const __half* pk_g = g_P + (size_t)b * SEQ * RNK;
    const __half* vh_g = g_xh + (size_t)b * SEQ * DIM + (size_t)z * 256;

    // ---- load Pq tile [128 q][64 r] into smem (swizzled) ----
#pragma unroll
    for (int m = 0; m < 4; m++) {
        int idx = t + 256 * m;
        int row = idx >> 3, ch = idx & 7;
        size_t src = ((size_t)b * SEQ + (size_t)qb * 128 + row) * RNK + ch * 8;
        uint32_t dst = row * 128 + (((uint32_t)(ch ^ (row & 7))) << 4);
        *(uint4*)(sm + OFF_PQ + dst) = *(const uint4*)(g_P + src);
    }
    // ---- prefetch tile 0 ----
    {
#pragma unroll
        for (int m = 0; m < 2; m++) {
            int idx = t + 256 * m;
            int row = idx >> 3, ch = idx & 7;
            uint32_t dsw = row * 128 + (((uint32_t)(ch ^ (row & 7))) << 4);
            CP16(smb + OFF_PK + dsw, pk_g + (size_t)row * RNK + ch * 8);
        }
#pragma unroll
        for (int m = 0; m < 8; m++) {
            int idx = t + 256 * m;
            int row = idx >> 5, ch = idx & 31;
            uint32_t dsw = row * 512 + (((uint32_t)(ch ^ (row & 7))) << 4);
            CP16(smb + OFF_V + dsw, vh_g + (size_t)row * DIM + ch * 8);
        }
        CP_COMMIT();
    }
    __syncthreads();

    // ---- hoist Pq A-fragments into registers ----
    const uint32_t rowA = q0 + i7 + ((grp & 1) << 3);
    const uint32_t cselA = grp >> 1;
    uint32_t aReg[4][4];
#pragma unroll
    for (int kt = 0; kt < 4; kt++)
        ldsm4(aReg[kt], smb + OFF_PQ + rowA * 128 + ((((kt << 1) + cselA) ^ i7) << 4));

    float Y[32][4];
#pragma unroll
    for (int n = 0; n < 32; n++)
#pragma unroll
        for (int e = 0; e < 4; e++) Y[n][e] = 0.f;
    float Ll = 0.f, Lh = 0.f;

    const uint32_t rowB = i7 + ((grp >> 1) << 3);
    const uint32_t cselB = grp & 1;
    const uint32_t rowV = i7 + ((grp & 1) << 3);
    const uint32_t cselV = grp >> 1;

    for (int it = 0; it < NIT; it++) {
        const int buf = it & 1;
        CP_WAIT0();
        __syncthreads();

        // prefetch tile it+1 (overlaps compute)
        if (it + 1 < NIT) {
            const int k0n = (it + 1) * KB;
            const int bo = buf ^ 1;
#pragma unroll
            for (int m = 0; m < 2; m++) {
                int idx = t + 256 * m;
                int row = idx >> 3, ch = idx & 7;
                uint32_t dsw = row * 128 + (((uint32_t)(ch ^ (row & 7))) << 4);
                CP16(smb + OFF_PK + bo * 8192 + dsw,
                     pk_g + (size_t)(k0n + row) * RNK + ch * 8);
            }
#pragma unroll
            for (int m = 0; m < 8; m++) {
                int idx = t + 256 * m;
                int row = idx >> 5, ch = idx & 31;
                uint32_t dsw = row * 512 + (((uint32_t)(ch ^ (row & 7))) << 4);
                CP16(smb + OFF_V + bo * 32768 + dsw,
                     vh_g + (size_t)(k0n + row) * DIM + ch * 8);
            }
            CP_COMMIT();
        }

        // ---- QK^T (single combo; logits pre-scaled by log2 e) ----
        float S[8][4];
#pragma unroll
        for (int n = 0; n < 8; n++)
#pragma unroll
            for (int e = 0; e < 4; e++) S[n][e] = 0.f;

        const uint32_t pkBase = smb + OFF_PK + buf * 8192;
#pragma unroll
        for (int kt = 0; kt < 4; kt++) {
#pragma unroll
            for (int np = 0; np < 4; np++) {
                uint32_t bh[4];
                ldsm4(bh, pkBase + ((np << 4) + rowB) * 128
                          + ((((kt << 1) + cselB) ^ i7) << 4));
                mma16816(S[2 * np],     aReg[kt], bh + 0);
                mma16816(S[2 * np + 1], aReg[kt], bh + 2);
            }
        }

        // ---- softmax probs via MUFU ex2; mean-shift for PV ----
        float rl = 0.f, rh = 0.f;
#pragma unroll
        for (int n = 0; n < 8; n++) {
            S[n][0] = ex2(S[n][0]);
            S[n][1] = ex2(S[n][1]);
            S[n][2] = ex2(S[n][2]);
            S[n][3] = ex2(S[n][3]);
            rl += S[n][0] + S[n][1];
            rh += S[n][2] + S[n][3];
        }
        rl += __shfl_xor_sync(0xffffffffu, rl, 1);
        rl += __shfl_xor_sync(0xffffffffu, rl, 2);
        rh += __shfl_xor_sync(0xffffffffu, rh, 1);
        rh += __shfl_xor_sync(0xffffffffu, rh, 2);
        Ll += rl;
        Lh += rh;

        uint32_t Ph[4][4];
#pragma unroll
        for (int kt = 0; kt < 4; kt++) {
            int n0 = 2 * kt;
            Ph[kt][0] = packh(S[n0][0] - 1.f,     S[n0][1] - 1.f);
            Ph[kt][1] = packh(S[n0][2] - 1.f,     S[n0][3] - 1.f);
            Ph[kt][2] = packh(S[n0 + 1][0] - 1.f, S[n0 + 1][1] - 1.f);
            Ph[kt][3] = packh(S[n0 + 1][2] - 1.f, S[n0 + 1][3] - 1.f);
        }

        // ---- PV: Y += (P-1) @ V ----
        const uint32_t vBase = smb + OFF_V + buf * 32768;
#pragma unroll
        for (int kt = 0; kt < 4; kt++) {
            uint32_t vrow = vBase + ((kt << 4) + rowV) * 512;
#pragma unroll
            for (int np = 0; np < 16; np++) {
                uint32_t bh[4];
                ldsm4t(bh, vrow + ((((np << 1) + cselV) ^ i7) << 4));
                mma16816(Y[2 * np],     Ph[kt], bh + 0);
                mma16816(Y[2 * np + 1], Ph[kt], bh + 2);
            }
        }
    }

    // ---- epilogue: y = (csum + Ydot) / l ----
    const float il = 1.0f / Ll;
    const float ih = 1.0f / Lh;
    const int rlo = qb * 128 + q0 + g;
    const float* cs_base = g_csum + b * DIM + z * 256 + 2 * tg;
    float* o_lo = out + ((size_t)b * SEQ + rlo) * DIM + (size_t)z * 256 + 2 * tg;
    float* o_hi = o_lo + (size_t)8 * DIM;
#pragma unroll
    for (int n = 0; n < 32; n++) {
        float2 cs = *(const float2*)(cs_base + 8 * n);
        float2 p;
        p.x = (Y[n][0] + cs.x) * il; p.y = (Y[n][1] + cs.y) * il;
        *(float2*)(o_lo + 8 * n) = p;
        p.x = (Y[n][2] + cs.x) * ih; p.y = (Y[n][3] + cs.y) * ih;
        *(float2*)(o_hi + 8 * n) = p;
    }
}

// ---------------------------------------------------------------------------
extern "C" void kernel_launch(void* const* d_in, const int* in_sizes, int n_in,
                              void* d_out, int out_size) {
    const float* x = (const float*)d_in[0];
    const float* Q = (const float*)d_in[1];
    float* out = (float*)d_out;

    cudaFuncSetAttribute(attn_kernel, cudaFuncAttributeMaxDynamicSharedMemorySize,
                         SMEM_TOTAL);
    cudaFuncSetAttribute(projH_kernel, cudaFuncAttributeMaxDynamicSharedMemorySize,
                         PSM_TOTAL);

    cvt_kernel<<<(size_t)BATCH * SEQ * DIM / 4 / 256, 256>>>(x);
    qprep_kernel<<<DIM / 64, 256>>>(Q);
    projH_kernel<<<BATCH * SEQ / 128, 256, PSM_TOTAL>>>();
    csum1_kernel<<<dim3(DIM / 64, BATCH, 8), 256>>>(x);
    csum2_kernel<<<BATCH * DIM / 256, 256>>>();
    attn_kernel<<<dim3(SEQ / 128, DIM / 256, BATCH), 256, SMEM_TOTAL>>>(out);
}